// round 14
// baseline (speedup 1.0000x reference)
#include <cuda_runtime.h>
#include <cstdint>

// VoxelPooling: out[n,:] = mean_{k<20} src_feat[idx(n,k), :]
// idx(n,k) = invoxel_map[n,k] (int32), 0 replaced by invoxel_map[n,0].
//
// Inputs: d_in[0] xyz (UNUSED), d_in[1] map int32 [N,20], d_in[2] src_feat f32 [M,16]
// Output: f32 [N,16]
//
// Two sequential passes over disjoint index halves of src_feat (64 MB each,
// partially L2-resident: measured 0.82 GB total DRAM vs 1.15 GB single-pass).
// Gathers are branchless predicated asm loads (no wavefront / no traffic when
// off). R12's register staging was silently undone by ptxas because the asm
// was not volatile (regs stayed 32, SASS unchanged). R14: `asm volatile`
// pins the 10-load batches in program order -> ~10 float4 loads in flight
// per thread -> L1tex queue saturates -> passes approach their DRAM (65us)
// and L1 (52us) floors instead of idling at 57% everywhere.

#define FUSE_K 20
#define G 10   // gather batch size (10 x float4 dests)

// Predicated 16B gather: zeros when !in, no memory access when off.
// volatile: ptxas must not sink/merge these - keeps the batch issued early.
__device__ __forceinline__ float4 ldg_pred(const float4* p, int in) {
    float4 r;
    asm volatile(
        "{\n\t"
        ".reg .pred q;\n\t"
        "setp.ne.s32 q, %5, 0;\n\t"
        "mov.f32 %0, 0f00000000;\n\t"
        "mov.f32 %1, 0f00000000;\n\t"
        "mov.f32 %2, 0f00000000;\n\t"
        "mov.f32 %3, 0f00000000;\n\t"
        "@q ld.global.nc.v4.f32 {%0,%1,%2,%3}, [%4];\n\t"
        "}"
        : "=f"(r.x), "=f"(r.y), "=f"(r.z), "=f"(r.w)
        : "l"(p), "r"(in));
    return r;
}

template <bool FIRST, bool LAST>
__global__ __launch_bounds__(256) void voxel_pool_pass(
    const int* __restrict__ invoxel_map,   // [N, FUSE_K] int32
    const float4* __restrict__ src_feat,   // [M,4] float4 view of [M,16]
    float4* __restrict__ out,              // [N,4] float4 view of [N,16]
    int N, int lo, int hi)
{
    int t = blockIdx.x * blockDim.x + threadIdx.x;
    int v  = t >> 2;        // voxel
    int cp = t & 3;         // float4 chunk of the 16 channels
    if (v >= N) return;

    // 20 indices via 5x int4 (row stride 80B, 16B aligned). Streaming.
    const int4* m = reinterpret_cast<const int4*>(invoxel_map + (long long)v * FUSE_K);
    int idx[FUSE_K];
#pragma unroll
    for (int q = 0; q < FUSE_K / 4; q++) {
        int4 p = __ldcs(&m[q]);
        idx[q * 4 + 0] = p.x;
        idx[q * 4 + 1] = p.y;
        idx[q * 4 + 2] = p.z;
        idx[q * 4 + 3] = p.w;
    }

    int first = idx[0];
#pragma unroll
    for (int k = 0; k < FUSE_K; k++)
        idx[k] = (idx[k] == 0) ? first : idx[k];

    float4 acc;
    if (FIRST) {
        acc = make_float4(0.f, 0.f, 0.f, 0.f);
    } else {
        acc = __ldcs(&out[(long long)v * 4 + cp]);   // partial sums (streaming)
    }

    // Batched predicated gathers: G volatile loads issue back-to-back into
    // dedicated registers, THEN the accumulates consume them.
#pragma unroll
    for (int c = 0; c < FUSE_K / G; c++) {
        float4 f[G];
#pragma unroll
        for (int j = 0; j < G; j++) {
            int id = idx[c * G + j];
            int in = (id >= lo) && (id < hi);
            f[j] = ldg_pred(&src_feat[id * 4 + cp], in);
        }
#pragma unroll
        for (int j = 0; j < G; j++) {
            acc.x += f[j].x;
            acc.y += f[j].y;
            acc.z += f[j].z;
            acc.w += f[j].w;
        }
    }

    if (LAST) {
        const float s = 1.0f / (float)FUSE_K;
        acc.x *= s; acc.y *= s; acc.z *= s; acc.w *= s;
    }
    __stcs(&out[(long long)v * 4 + cp], acc);
}

extern "C" void kernel_launch(void* const* d_in, const int* in_sizes, int n_in,
                              void* d_out, int out_size)
{
    const int*    invoxel_map = (const int*)d_in[1];
    const float4* src_feat    = (const float4*)d_in[2];
    float4*       out         = (float4*)d_out;

    int N = in_sizes[1] / FUSE_K;     // voxels
    int M = in_sizes[2] / 16;         // src_feat rows
    int half = M / 2;

    int threads_needed = N * 4;       // 4 lanes per voxel
    int block = 256;
    int grid  = (threads_needed + block - 1) / block;

    voxel_pool_pass<true,  false><<<grid, block>>>(invoxel_map, src_feat, out, N, 0,    half);
    voxel_pool_pass<false, true ><<<grid, block>>>(invoxel_map, src_feat, out, N, half, M);
}

// round 17
// speedup vs baseline: 1.2425x; 1.2425x over previous
#include <cuda_runtime.h>
#include <cuda_fp16.h>
#include <cstdint>
#include <cstring>

// VoxelPooling: out[n,:] = mean_{k<20} src_feat[idx(n,k), :]
// idx(n,k) = invoxel_map[n,k] (int32), 0 replaced by invoxel_map[n,0].
//
// Inputs: d_in[0] xyz (UNUSED), d_in[1] map int32 [N,20], d_in[2] src_feat f32 [M,16]
// Output: f32 [N,16]
//
// Strategy: the 128 MB fp32 gather table thrashes the ~126 MB L2 (78% miss,
// 1.15 GB DRAM single-pass; split passes capped ~4.7 TB/s regardless of
// schedule). Fix the BYTES: convert src_feat to a 64 MB fp16 __device__
// scratch table (~30 us streaming), then single-pass gather against the fp16
// table, which fits in L2 and is L2-warm from the convert writes. fp32
// accumulate; rel_err ~2e-4 << 1e-3 tolerance.

#define FUSE_K 20
#define M_CAP 2000000   // capacity of the fp16 scratch table (rows)

__device__ __half g_feat16[(size_t)M_CAP * 16];   // 64 MB static scratch

__device__ __forceinline__ unsigned h2_bits(__half2 h) {
    unsigned u;
    memcpy(&u, &h, 4);
    return u;
}

// ---------------- convert: fp32 [M,16] -> fp16 scratch ----------------
// one thread per 8 elements (reads 2 float4 streaming, writes one uint4)
__global__ __launch_bounds__(256) void convert_kernel(
    const float4* __restrict__ src, int n8)
{
    int i = blockIdx.x * blockDim.x + threadIdx.x;
    if (i >= n8) return;

    float4 a = __ldcs(&src[(size_t)i * 2]);      // streaming read (no reuse)
    float4 b = __ldcs(&src[(size_t)i * 2 + 1]);

    uint4 pack;
    pack.x = h2_bits(__floats2half2_rn(a.x, a.y));
    pack.y = h2_bits(__floats2half2_rn(a.z, a.w));
    pack.z = h2_bits(__floats2half2_rn(b.x, b.y));
    pack.w = h2_bits(__floats2half2_rn(b.z, b.w));

    // default-policy store: leaves the table lines resident in L2
    reinterpret_cast<uint4*>(g_feat16)[i] = pack;
}

// ---------------- gather: fp16 table, fp32 accumulate ----------------
// 2 lanes per voxel, each lane owns 8 channels (16 B of fp16).
__global__ __launch_bounds__(256) void gather16_kernel(
    const int* __restrict__ invoxel_map,   // [N, FUSE_K] int32
    float4* __restrict__ out,              // [N,4] float4 view of [N,16]
    int N)
{
    int t = blockIdx.x * blockDim.x + threadIdx.x;
    int v  = t >> 1;        // voxel
    int cp = t & 1;         // which 8-channel half
    if (v >= N) return;

    // 20 indices via 5x int4 (row stride 80 B, 16 B aligned). Streaming.
    const int4* m = reinterpret_cast<const int4*>(invoxel_map + (long long)v * FUSE_K);
    int idx[FUSE_K];
#pragma unroll
    for (int q = 0; q < FUSE_K / 4; q++) {
        int4 p = __ldcs(&m[q]);
        idx[q * 4 + 0] = p.x;
        idx[q * 4 + 1] = p.y;
        idx[q * 4 + 2] = p.z;
        idx[q * 4 + 3] = p.w;
    }

    int first = idx[0];
#pragma unroll
    for (int k = 0; k < FUSE_K; k++)
        idx[k] = (idx[k] == 0) ? first : idx[k];

    // Straight-line unconditional gathers (R2-style deep batching).
    const uint4* tbl = reinterpret_cast<const uint4*>(g_feat16);
    float2 a0 = make_float2(0.f, 0.f);
    float2 a1 = make_float2(0.f, 0.f);
    float2 a2 = make_float2(0.f, 0.f);
    float2 a3 = make_float2(0.f, 0.f);

#pragma unroll
    for (int k = 0; k < FUSE_K; k++) {
        uint4 u = __ldg(&tbl[(size_t)idx[k] * 2 + cp]);   // 16 B = 8 halves
        __half2 h0, h1, h2, h3;
        memcpy(&h0, &u.x, 4);
        memcpy(&h1, &u.y, 4);
        memcpy(&h2, &u.z, 4);
        memcpy(&h3, &u.w, 4);
        float2 f0 = __half22float2(h0);
        float2 f1 = __half22float2(h1);
        float2 f2 = __half22float2(h2);
        float2 f3 = __half22float2(h3);
        a0.x += f0.x; a0.y += f0.y;
        a1.x += f1.x; a1.y += f1.y;
        a2.x += f2.x; a2.y += f2.y;
        a3.x += f3.x; a3.y += f3.y;
    }

    const float s = 1.0f / (float)FUSE_K;
    long long o = (long long)v * 4 + cp * 2;
    __stcs(&out[o],     make_float4(a0.x * s, a0.y * s, a1.x * s, a1.y * s));
    __stcs(&out[o + 1], make_float4(a2.x * s, a2.y * s, a3.x * s, a3.y * s));
}

// ---------------- fp32 fallback (if M exceeds scratch capacity) ----------------
__global__ __launch_bounds__(256) void voxel_pool_f32(
    const int* __restrict__ invoxel_map,
    const float4* __restrict__ src_feat,
    float4* __restrict__ out,
    int N)
{
    int t = blockIdx.x * blockDim.x + threadIdx.x;
    int v  = t >> 2;
    int cp = t & 3;
    if (v >= N) return;

    const int4* m = reinterpret_cast<const int4*>(invoxel_map + (long long)v * FUSE_K);
    int idx[FUSE_K];
#pragma unroll
    for (int q = 0; q < FUSE_K / 4; q++) {
        int4 p = __ldcs(&m[q]);
        idx[q * 4 + 0] = p.x;
        idx[q * 4 + 1] = p.y;
        idx[q * 4 + 2] = p.z;
        idx[q * 4 + 3] = p.w;
    }
    int first = idx[0];
#pragma unroll
    for (int k = 0; k < FUSE_K; k++)
        idx[k] = (idx[k] == 0) ? first : idx[k];

    float4 acc = make_float4(0.f, 0.f, 0.f, 0.f);
#pragma unroll
    for (int k = 0; k < FUSE_K; k++) {
        float4 f = __ldg(&src_feat[idx[k] * 4 + cp]);
        acc.x += f.x; acc.y += f.y; acc.z += f.z; acc.w += f.w;
    }
    const float s = 1.0f / (float)FUSE_K;
    acc.x *= s; acc.y *= s; acc.z *= s; acc.w *= s;
    __stcs(&out[(long long)v * 4 + cp], acc);
}

extern "C" void kernel_launch(void* const* d_in, const int* in_sizes, int n_in,
                              void* d_out, int out_size)
{
    const int*    invoxel_map = (const int*)d_in[1];
    const float4* src_feat    = (const float4*)d_in[2];
    float4*       out         = (float4*)d_out;

    int N = in_sizes[1] / FUSE_K;     // voxels
    int M = in_sizes[2] / 16;         // src_feat rows
    int block = 256;

    if (M <= M_CAP) {
        // 1) convert fp32 table -> fp16 scratch (64 MB, L2-resident)
        int n8 = M * 2;               // groups of 8 elements
        int grid_c = (n8 + block - 1) / block;
        convert_kernel<<<grid_c, block>>>(src_feat, n8);

        // 2) single-pass gather against the fp16 table
        int threads_needed = N * 2;   // 2 lanes per voxel
        int grid_g = (threads_needed + block - 1) / block;
        gather16_kernel<<<grid_g, block>>>(invoxel_map, out, N);
    } else {
        int threads_needed = N * 4;
        int grid = (threads_needed + block - 1) / block;
        voxel_pool_f32<<<grid, block>>>(invoxel_map, src_feat, out, N);
    }
}